// round 17
// baseline (speedup 1.0000x reference)
#include <cuda_runtime.h>
#include <cuda_bf16.h>
#include <cuda_fp8.h>
#include <math.h>
#include <cstdint>

#define C 1024
#define BATCH 16
#define D 128
#define CB (C*BATCH)
#define CC (C*C)

#define LDK 72
#define LDKB 144
#define TILE_E (128*LDK)
#define TILE_B (TILE_E*2)          // 18432
#define WTILE_B (2*TILE_B)         // 36864
#define BUF2_B (2*TILE_B)
#define BUF3_B (3*TILE_B)
#define GSLOT_B (2*TILE_B + 2*WTILE_B)  // 110592

#define LDK8 144
#define TILE8_B (128*LDK8)

// ---------------- scratch ----------------------------------------------------
__device__ uint8_t g_F8[BATCH*CC];
__device__ uint8_t g_GT8[BATCH*CC];
__device__ float g_sumF[BATCH*C];            // zeroed by gate tail / load-init
__device__ float g_sumG[BATCH*C];
__device__ float g_sum2[BATCH*C];
__device__ __nv_bfloat16 g_E2[BATCH*CC];
__device__ __nv_bfloat16 g_hhi[CB*D];
__device__ __nv_bfloat16 g_hlo[CB*D];
__device__ __nv_bfloat16 g_h1hi[CB*D];
__device__ __nv_bfloat16 g_h1lo[CB*D];
__device__ __nv_bfloat16 g_h2hi[CB*D];
__device__ __nv_bfloat16 g_h2lo[CB*D];
__device__ __nv_bfloat16 g_hThi[BATCH*D*C];
__device__ __nv_bfloat16 g_hTlo[BATCH*D*C];
__device__ __nv_bfloat16 g_mhi[(size_t)CB*384];
__device__ __nv_bfloat16 g_mlo[(size_t)CB*384];
__device__ __nv_bfloat16 g_Whi[256*384];
__device__ __nv_bfloat16 g_Wlo[256*384];
__device__ __nv_bfloat16 g_Vhi[256*128];
__device__ __nv_bfloat16 g_Vlo[256*128];
__device__ float g_bias[256];

// ----------------------------------------------------------------- helpers
__device__ __forceinline__ uint32_t smem_u32(const void* p) {
    uint32_t a;
    asm("{ .reg .u64 t; cvta.to.shared.u64 t, %1; cvt.u32.u64 %0, t; }" : "=r"(a) : "l"(p));
    return a;
}
__device__ __forceinline__ void mma16816(float* c, const uint32_t* a, const uint32_t* b) {
    asm volatile(
        "mma.sync.aligned.m16n8k16.row.col.f32.bf16.bf16.f32 "
        "{%0,%1,%2,%3}, {%4,%5,%6,%7}, {%8,%9}, {%0,%1,%2,%3};"
        : "+f"(c[0]), "+f"(c[1]), "+f"(c[2]), "+f"(c[3])
        : "r"(a[0]), "r"(a[1]), "r"(a[2]), "r"(a[3]), "r"(b[0]), "r"(b[1]));
}
__device__ __forceinline__ void mma16832f8(float* c, const uint32_t* a, const uint32_t* b) {
    asm volatile(
        "mma.sync.aligned.m16n8k32.row.col.f32.e4m3.e4m3.f32 "
        "{%0,%1,%2,%3}, {%4,%5,%6,%7}, {%8,%9}, {%0,%1,%2,%3};"
        : "+f"(c[0]), "+f"(c[1]), "+f"(c[2]), "+f"(c[3])
        : "r"(a[0]), "r"(a[1]), "r"(a[2]), "r"(a[3]), "r"(b[0]), "r"(b[1]));
}
__device__ __forceinline__ void ldsm4(uint32_t a, uint32_t* r) {
    asm volatile("ldmatrix.sync.aligned.m8n8.x4.shared.b16 {%0,%1,%2,%3}, [%4];"
        : "=r"(r[0]), "=r"(r[1]), "=r"(r[2]), "=r"(r[3]) : "r"(a));
}
__device__ __forceinline__ void cp16(uint32_t s, const void* g) {
    asm volatile("cp.async.cg.shared.global [%0], [%1], 16;" :: "r"(s), "l"(g));
}
#define CP_COMMIT() asm volatile("cp.async.commit_group;" ::: "memory")
#define CP_WAITN(n) asm volatile("cp.async.wait_group %0;" :: "n"(n) : "memory")

__device__ __forceinline__ void split2(float2 v, __nv_bfloat162& hi, __nv_bfloat162& lo) {
    hi.x = __float2bfloat16(v.x); lo.x = __float2bfloat16(v.x - __bfloat162float(hi.x));
    hi.y = __float2bfloat16(v.y); lo.y = __float2bfloat16(v.y - __bfloat162float(hi.y));
}
__device__ __forceinline__ uint8_t to_e4m3(float x) {
    return (uint8_t)__nv_cvt_float_to_fp8(x, __NV_SATFINITE, __NV_E4M3);
}

__device__ __forceinline__ uint32_t a_lane_off(int warp_row, int lid) {
    int mi = lid >> 3, l7 = lid & 7;
    return (uint32_t)((warp_row + (mi & 1)*8 + l7)*LDKB + (mi >> 1)*16);
}
__device__ __forceinline__ uint32_t b_lane_off(int warp_col, int lid) {
    int mi = lid >> 3, l7 = lid & 7;
    return (uint32_t)((warp_col + (mi >> 1)*8 + l7)*LDKB + (mi & 1)*16);
}

// load one 2-tile bf16 chunk (A, B), 128 rows x 64 bf16 each
__device__ __forceinline__ void issue_single(
    uint32_t sb, int tid,
    const __nv_bfloat16* A, const __nv_bfloat16* Bp, size_t rs)
{
#pragma unroll
    for (int q = 0; q < 4; q++) {
        int idx = q*256 + tid;
        int row = idx >> 3, seg = idx & 7;
        size_t g = (size_t)row*rs + seg*8;
        uint32_t so = row*LDKB + seg*16;
        cp16(sb +          so, A  + g);
        cp16(sb + TILE_B + so, Bp + g);
    }
}

// load one 2-tile fp8 chunk (A, B), 128 rows x 128 e4m3 bytes each (K=128)
__device__ __forceinline__ void issue_fp8_128(
    uint32_t sb, int tid, const uint8_t* A, const uint8_t* Bp, size_t rs)
{
#pragma unroll
    for (int q = 0; q < 8; q++) {
        int idx = q*256 + tid;
        int tile = idx >> 10;
        int row  = (idx >> 3) & 127;
        int seg  = idx & 7;
        const uint8_t* src = tile ? Bp : A;
        cp16(sb + tile*TILE8_B + row*LDK8 + seg*16,
             src + (size_t)row*rs + seg*16);
    }
}

// load one 3-tile bf16 chunk (A, Bh, Bl)
__device__ __forceinline__ void issue_tiles3(
    uint32_t sb, int tid,
    const __nv_bfloat16* A,
    const __nv_bfloat16* Bh, const __nv_bfloat16* Bl,
    size_t rsA, size_t rsB)
{
#pragma unroll
    for (int q = 0; q < 4; q++) {
        int idx = q*256 + tid;
        int row = idx >> 3, seg = idx & 7;
        size_t gA = (size_t)row*rsA + seg*8;
        size_t gB = (size_t)row*rsB + seg*8;
        uint32_t so = row*LDKB + seg*16;
        cp16(sb +            so, A  + gA);
        cp16(sb +   TILE_B + so, Bh + gB);
        cp16(sb + 2*TILE_B + so, Bl + gB);
    }
}

// gate/fc chunk load: A (hi/lo, 128 rows) + W (hi/lo, 256 rows)
__device__ __forceinline__ void issue_gate(
    uint32_t sb, int tid,
    const __nv_bfloat16* Ah, const __nv_bfloat16* Al,
    const __nv_bfloat16* Wh, const __nv_bfloat16* Wl, size_t rs)
{
#pragma unroll
    for (int q = 0; q < 4; q++) {
        int idx = q*256 + tid;
        int row = idx >> 3, seg = idx & 7;
        size_t g = (size_t)row*rs + seg*8;
        uint32_t so = row*LDKB + seg*16;
        cp16(sb +          so, Ah + g);
        cp16(sb + TILE_B + so, Al + g);
    }
#pragma unroll
    for (int q = 0; q < 8; q++) {
        int idx = q*256 + tid;
        int row = idx >> 3, seg = idx & 7;
        size_t g = (size_t)row*rs + seg*8;
        uint32_t so = row*LDKB + seg*16;
        cp16(sb + 2*TILE_B +           so, Wh + g);
        cp16(sb + 2*TILE_B + WTILE_B + so, Wl + g);
    }
}

// bf16 single-precision chunk (K=64)
__device__ __forceinline__ void compute_chunk1(
    uint32_t sA, uint32_t sB, float acc[4][4][4], int wm, int wn, int lid)
{
    uint32_t aoff = sA + a_lane_off(wm*64, lid);
    uint32_t boff = sB + b_lane_off(wn*32, lid);
#pragma unroll
    for (int ks = 0; ks < 4; ks++) {
        uint32_t a[4][4], bb[2][4];
#pragma unroll
        for (int im = 0; im < 4; im++) ldsm4(aoff + im*(16*LDKB) + ks*32, a[im]);
#pragma unroll
        for (int p = 0; p < 2; p++)  ldsm4(boff + p*(16*LDKB) + ks*32, bb[p]);
#pragma unroll
        for (int im = 0; im < 4; im++)
#pragma unroll
            for (int jn = 0; jn < 4; jn++)
                mma16816(acc[im][jn], a[im], &bb[jn>>1][(jn&1)*2]);
    }
}

// fp8 chunk (K=128)
__device__ __forceinline__ void compute_chunk_fp8(
    uint32_t sA, uint32_t sB, float acc[4][4][4], int wm, int wn, int lid)
{
    uint32_t aoff = sA + a_lane_off(wm*64, lid);
    uint32_t boff = sB + b_lane_off(wn*32, lid);
#pragma unroll
    for (int ks = 0; ks < 4; ks++) {
        uint32_t a[4][4], bb[2][4];
#pragma unroll
        for (int im = 0; im < 4; im++) ldsm4(aoff + im*(16*LDKB) + ks*32, a[im]);
#pragma unroll
        for (int p = 0; p < 2; p++)  ldsm4(boff + p*(16*LDKB) + ks*32, bb[p]);
#pragma unroll
        for (int im = 0; im < 4; im++)
#pragma unroll
            for (int jn = 0; jn < 4; jn++)
                mma16832f8(acc[im][jn], a[im], &bb[jn>>1][(jn&1)*2]);
    }
}

// 2-mma chunk (A single, B hi/lo)
__device__ __forceinline__ void compute_chunk2(
    uint32_t base, float acc[4][4][4], int wm, int wn, int lid)
{
    uint32_t aoff  = base +            a_lane_off(wm*64, lid);
    uint32_t boffh = base +   TILE_B + b_lane_off(wn*32, lid);
    uint32_t boffl = base + 2*TILE_B + b_lane_off(wn*32, lid);
#pragma unroll
    for (int ks = 0; ks < 4; ks++) {
        uint32_t a[4][4], bh[2][4], bl[2][4];
#pragma unroll
        for (int im = 0; im < 4; im++) ldsm4(aoff + im*(16*LDKB) + ks*32, a[im]);
#pragma unroll
        for (int p = 0; p < 2; p++) {
            ldsm4(boffh + p*(16*LDKB) + ks*32, bh[p]);
            ldsm4(boffl + p*(16*LDKB) + ks*32, bl[p]);
        }
#pragma unroll
        for (int im = 0; im < 4; im++)
#pragma unroll
            for (int jn = 0; jn < 4; jn++) {
                mma16816(acc[im][jn], a[im], &bh[jn>>1][(jn&1)*2]);
                mma16816(acc[im][jn], a[im], &bl[jn>>1][(jn&1)*2]);
            }
    }
}

// gate/fc chunk: 3-mma split, dual B halves
__device__ __forceinline__ void compute_gate(
    uint32_t base, float accR[4][4][4], float accG[4][4][4],
    int wm, int wn, int lid)
{
    uint32_t aoffh = base +          a_lane_off(wm*64, lid);
    uint32_t aoffl = base + TILE_B + a_lane_off(wm*64, lid);
    uint32_t wh = base + 2*TILE_B;
    uint32_t wl = wh + WTILE_B;
    uint32_t bRh = wh + b_lane_off(wn*32, lid);
    uint32_t bGh = wh + b_lane_off(128 + wn*32, lid);
    uint32_t bRl = wl + b_lane_off(wn*32, lid);
    uint32_t bGl = wl + b_lane_off(128 + wn*32, lid);
#pragma unroll
    for (int ks = 0; ks < 4; ks++) {
        uint32_t ah[4][4], al[4][4];
        uint32_t rh[2][4], rl[2][4], gh[2][4], gl[2][4];
#pragma unroll
        for (int im = 0; im < 4; im++) {
            ldsm4(aoffh + im*(16*LDKB) + ks*32, ah[im]);
            ldsm4(aoffl + im*(16*LDKB) + ks*32, al[im]);
        }
#pragma unroll
        for (int p = 0; p < 2; p++) {
            ldsm4(bRh + p*(16*LDKB) + ks*32, rh[p]);
            ldsm4(bRl + p*(16*LDKB) + ks*32, rl[p]);
            ldsm4(bGh + p*(16*LDKB) + ks*32, gh[p]);
            ldsm4(bGl + p*(16*LDKB) + ks*32, gl[p]);
        }
#pragma unroll
        for (int im = 0; im < 4; im++)
#pragma unroll
            for (int jn = 0; jn < 4; jn++) {
                mma16816(accR[im][jn], ah[im], &rh[jn>>1][(jn&1)*2]);
                mma16816(accR[im][jn], ah[im], &rl[jn>>1][(jn&1)*2]);
                mma16816(accR[im][jn], al[im], &rh[jn>>1][(jn&1)*2]);
                mma16816(accG[im][jn], ah[im], &gh[jn>>1][(jn&1)*2]);
                mma16816(accG[im][jn], ah[im], &gl[jn>>1][(jn&1)*2]);
                mma16816(accG[im][jn], al[im], &gh[jn>>1][(jn&1)*2]);
            }
    }
}

// =================== merged prep: ht+h-split | esplit | weight folds =========
#define LDT 132
__global__ void __launch_bounds__(256) prep_kernel(
    const float* __restrict__ h,
    const float* __restrict__ Bt, const int* __restrict__ mask,
    const float* __restrict__ Wr, const float* __restrict__ Wg,
    const float* __restrict__ W1, const float* __restrict__ W2,
    const float* __restrict__ b1, const float* __restrict__ b2)
{
    __shared__ uint8_t tile[128*LDT];
    __shared__ float scol[128];
    int bid = blockIdx.x;

    if (bid < 2048) {
        // ---------------- ht transpose + h hi/lo row split ----------------
        float* tileT = (float*)tile;               // [32][33]
        int b  = bid >> 7;
        int d0 = ((bid >> 5) & 3) * 32;
        int c0 = (bid & 31) * 32;
        int tx = threadIdx.x & 31, ty = threadIdx.x >> 5;
#pragma unroll
        for (int r = ty; r < 32; r += 8) {
            size_t hidx = (size_t)((c0 + r)*16 + b)*128 + d0 + tx;
            float x = h[hidx];
            tileT[r*33 + tx] = x;
            __nv_bfloat16 hi = __float2bfloat16(x);
            g_hhi[hidx] = hi;
            g_hlo[hidx] = __float2bfloat16(x - __bfloat162float(hi));
        }
        __syncthreads();
#pragma unroll
        for (int r = ty; r < 32; r += 8) {
            float x = tileT[tx*33 + r];
            __nv_bfloat16 hi = __float2bfloat16(x);
            __nv_bfloat16 lo = __float2bfloat16(x - __bfloat162float(hi));
            size_t o = (size_t)b*D*C + (size_t)(d0 + r)*C + c0 + tx;
            g_hThi[o] = hi;
            g_hTlo[o] = lo;
        }
    } else if (bid < 3072) {
        // ---------------- esplit (sums pre-zeroed by prior gate) ----------
        int f2 = bid - 2048;
        int b  = f2 >> 6;
        int x0 = ((f2 >> 3) & 7) * 128;
        int y0 = (f2 & 7) * 128;
        int w = threadIdx.x >> 5, lid = threadIdx.x & 31;

        if (threadIdx.x < 128) scol[threadIdx.x] = 0.f;
        __syncthreads();

        int4 my4 = *(const int4*)(mask + b*C + y0 + lid*4);
        float yf0 = my4.x ? 1.f : 0.f, yf1 = my4.y ? 1.f : 0.f;
        float yf2 = my4.z ? 1.f : 0.f, yf3 = my4.w ? 1.f : 0.f;
        uint32_t ymask = (my4.x ? 0xFFu : 0) | (my4.y ? 0xFF00u : 0)
                       | (my4.z ? 0xFF0000u : 0) | (my4.w ? 0xFF000000u : 0);

        float gs0 = 0.f, gs1 = 0.f, gs2 = 0.f, gs3 = 0.f;
#pragma unroll 4
        for (int i = 0; i < 16; i++) {
            int xl = w*16 + i;
            int x = x0 + xl;
            float4 v = *(const float4*)(Bt + (size_t)b*CC + (size_t)x*C + y0 + lid*4);
            float e0 = __expf(v.x), e1 = __expf(v.y), e2 = __expf(v.z), e3 = __expf(v.w);
            float s = e0*yf0 + e1*yf1 + e2*yf2 + e3*yf3;
#pragma unroll
            for (int o = 16; o > 0; o >>= 1) s += __shfl_xor_sync(0xffffffffu, s, o);
            if (lid == 0) atomicAdd(g_sumF + b*C + x, s);
            uint32_t pk =  (uint32_t)to_e4m3(e0)        | ((uint32_t)to_e4m3(e1) << 8)
                        | ((uint32_t)to_e4m3(e2) << 16) | ((uint32_t)to_e4m3(e3) << 24);
            *(uint32_t*)(tile + xl*LDT + lid*4) = pk;
            *(uint32_t*)(g_F8 + (size_t)b*CC + (size_t)x*C + y0 + lid*4) = pk & ymask;
            float mrow = mask[b*C + x] ? 1.f : 0.f;
            gs0 += e0*mrow; gs1 += e1*mrow; gs2 += e2*mrow; gs3 += e3*mrow;
        }
        atomicAdd(&scol[lid*4 + 0], gs0);
        atomicAdd(&scol[lid*4 + 1], gs1);
        atomicAdd(&scol[lid*4 + 2], gs2);
        atomicAdd(&scol[lid*4 + 3], gs3);
        __syncthreads();
        if (threadIdx.x < 128)
            atomicAdd(g_sumG + b*C + y0 + threadIdx.x, scol[threadIdx.x]);

        int xq = lid*4;
        const int* mk = mask + b*C + x0 + xq;
        uint32_t xmask = (mk[0] ? 0xFFu : 0) | (mk[1] ? 0xFF00u : 0)
                       | (mk[2] ? 0xFF0000u : 0) | (mk[3] ? 0xFF000000u : 0);
#pragma unroll 4
        for (int i = 0; i < 16; i++) {
            int yl = w*16 + i;
            int y = y0 + yl;
            uint32_t pk =  (uint32_t)tile[(xq+0)*LDT + yl]
                        | ((uint32_t)tile[(xq+1)*LDT + yl] << 8)
                        | ((uint32_t)tile[(xq+2)*LDT + yl] << 16)
                        | ((uint32_t)tile[(xq+3)*LDT + yl] << 24);
            *(uint32_t*)(g_GT8 + (size_t)b*CC + (size_t)y*C + x0 + xq) = pk & xmask;
        }
    } else {
        // ---------------- weight folds (gate W', fc V, bias) --------------
        int idx = (bid - 3072)*256 + threadIdx.x;    // 0..98303
        if (idx < 256*128) {
            int n = idx >> 7, k = idx & 127;
            float x = (n < 128) ? W1[n*128 + k] : W2[(n-128)*128 + k];
            __nv_bfloat16 hi = __float2bfloat16(x);
            g_Vhi[idx] = hi;
            g_Vlo[idx] = __float2bfloat16(x - __bfloat162float(hi));
        }
        if (idx < 256) g_bias[idx] = (idx < 128) ? b1[idx] : b2[idx - 128];

        int n = idx / 384, k = idx % 384;
        const float* W = (n < 128) ? (Wr + n*512) : (Wg + (n-128)*512);
        float x;
        if (k < 128)       x = W[k] + W[384 + k];
        else if (k < 256)  x = W[k] - W[k + 256];     // W1 - W3
        else               x = W[k];
        __nv_bfloat16 hi = __float2bfloat16(x);
        g_Whi[idx] = hi;
        g_Wlo[idx] = __float2bfloat16(x - __bfloat162float(hi));
    }
}

// ============ fc GEMM (mma): h1/h2 = relu(h.[W1;W2]^T + bias) ================
__global__ void __launch_bounds__(256) fc_mma_kernel()
{
    extern __shared__ char smc[];
    int tid = threadIdx.x, wid = tid >> 5, lid = tid & 31;
    int bm = blockIdx.x;
    int wm = wid & 1, wn = wid >> 1;
    uint32_t sb = smem_u32(smc);

    float accR[4][4][4] = {}, accG[4][4][4] = {};

    auto issue = [&](int c) {
        size_t offA = ((size_t)bm*128)*128 + (size_t)c*64;
        size_t offW = (size_t)c*64;
        issue_gate(sb + (uint32_t)(c & 1)*GSLOT_B, tid,
                   g_hhi + offA, g_hlo + offA,
                   g_Vhi + offW, g_Vlo + offW, 128);
    };

    issue(0); CP_COMMIT();
    for (int c = 0; c < 2; c++) {
        CP_WAITN(0);
        __syncthreads();
        if (c + 1 < 2) { issue(c + 1); CP_COMMIT(); }
        compute_gate(sb + (uint32_t)(c & 1)*GSLOT_B, accR, accG, wm, wn, lid);
    }

    int lrow = lid >> 2, lcol2 = (lid & 3) << 1;
    int r0 = bm*128 + wm*64 + lrow;
#pragma unroll
    for (int im = 0; im < 4; im++) {
#pragma unroll
        for (int half = 0; half < 2; half++) {
            int r = r0 + im*16 + half*8;
            int cc = r >> 4, b = r & 15;
            size_t base = ((size_t)(b*C + cc))*D;
#pragma unroll
            for (int jn = 0; jn < 4; jn++) {
                int e = wn*32 + jn*8 + lcol2;
                float v0 = fmaxf(accR[im][jn][half*2]   + g_bias[e],     0.f);
                float v1 = fmaxf(accR[im][jn][half*2+1] + g_bias[e+1],   0.f);
                float w0 = fmaxf(accG[im][jn][half*2]   + g_bias[128+e],   0.f);
                float w1 = fmaxf(accG[im][jn][half*2+1] + g_bias[128+e+1], 0.f);
                __nv_bfloat162 hi, lo;
                split2(make_float2(v0, v1), hi, lo);
                *(__nv_bfloat162*)(g_h1hi + base + e) = hi;
                *(__nv_bfloat162*)(g_h1lo + base + e) = lo;
                split2(make_float2(w0, w1), hi, lo);
                *(__nv_bfloat162*)(g_h2hi + base + e) = hi;
                *(__nv_bfloat162*)(g_h2lo + base + e) = lo;
            }
        }
    }
}

// ============================ B_new GEMM + fused softmax epilogue ===========
__global__ void __launch_bounds__(256, 2) bnew_mma_kernel(
    const float* __restrict__ gamma_p, const int* __restrict__ mask,
    float* __restrict__ out)
{
    extern __shared__ char smc[];
    __shared__ int   sMask[128];
    __shared__ float sRow[128];
    int tid = threadIdx.x, wid = tid >> 5, lid = tid & 31;
    int b = blockIdx.z, it = blockIdx.y, jt = blockIdx.x;
    int wm = wid & 1, wn = wid >> 1;
    uint32_t sb = smem_u32(smc);

    if (tid < 128) { sMask[tid] = mask[b*C + jt*128 + tid]; sRow[tid] = 0.f; }

    float acc[4][4][4] = {};
    float gma = gamma_p[0];
    int lrow = lid >> 2, lcol2 = (lid & 3) << 1;

    // prefetch normalization factors (ready before launch)
    float invR[8], invCv[8];
#pragma unroll
    for (int im = 0; im < 4; im++) {
        int r = it*128 + wm*64 + lrow + im*16;
        invR[2*im]   = gma / g_sumF[b*C + r];
        invR[2*im+1] = gma / g_sumF[b*C + r + 8];
    }
#pragma unroll
    for (int jn = 0; jn < 4; jn++) {
        int cj = jt*128 + wn*32 + lcol2 + jn*8;
        invCv[2*jn]   = 1.0f / g_sumG[b*C + cj];
        invCv[2*jn+1] = 1.0f / g_sumG[b*C + cj + 1];
    }

    auto issue = [&](int c) {
        uint32_t slot = sb + (uint32_t)(c % 3)*BUF2_B;
        if (c < 8) {
            const uint8_t* A  = g_F8  + ((size_t)b*C + (size_t)it*128)*C + (size_t)c*128;
            const uint8_t* Bp = g_GT8 + ((size_t)b*C + (size_t)jt*128)*C + (size_t)c*128;
            issue_fp8_128(slot, tid, A, Bp, C);
        } else {
            int tm = (c - 8) >> 1, kh = (c - 8) & 1;
            const __nv_bfloat16* A1 = (tm < 2)  ? g_h1hi : g_h1lo;
            const __nv_bfloat16* B1 = (tm == 1) ? g_h2lo : g_h2hi;
            issue_single(slot, tid,
                         A1 + ((size_t)b*C + (size_t)it*128)*D + kh*64,
                         B1 + ((size_t)b*C + (size_t)jt*128)*D + kh*64, D);
        }
    };

    issue(0); CP_COMMIT();
    issue(1); CP_COMMIT();

    for (int c = 0; c < 14; c++) {
        if (c == 13) CP_WAITN(0); else CP_WAITN(1);
        __syncthreads();
        if (c == 8) {
#pragma unroll
            for (int im = 0; im < 4; im++)
#pragma unroll
                for (int jn = 0; jn < 4; jn++) {
                    acc[im][jn][0] *= invR[2*im]   * invCv[2*jn];
                    acc[im][jn][1] *= invR[2*im]   * invCv[2*jn+1];
                    acc[im][jn][2] *= invR[2*im+1] * invCv[2*jn];
                    acc[im][jn][3] *= invR[2*im+1] * invCv[2*jn+1];
                }
        }
        if (c + 2 < 14) { issue(c + 2); CP_COMMIT(); }
        uint32_t base = sb + (uint32_t)(c % 3)*BUF2_B;
        if (c < 8) compute_chunk_fp8(base, base + TILE8_B, acc, wm, wn, lid);
        else       compute_chunk1(base, base + TILE_B, acc, wm, wn, lid);
    }

    // ---- epilogue: diag zero, store fp32, fused masked exp (single bf16) ----
    int gi0 = it*128 + wm*64 + lrow;
    int gj0 = jt*128 + wn*32 + lcol2;
    float* obase = out + (size_t)b*CC;
#pragma unroll
    for (int im = 0; im < 4; im++) {
        int r = gi0 + im*16;
        float rp0 = 0.f, rp1 = 0.f;
#pragma unroll
        for (int jn = 0; jn < 4; jn++) {
            int cj = gj0 + jn*8;
            int lc = wn*32 + lcol2 + jn*8;
            float2 v0 = make_float2(acc[im][jn][0], acc[im][jn][1]);
            float2 v1 = make_float2(acc[im][jn][2], acc[im][jn][3]);
            if (r == cj)        v0.x = 0.f;
            else if (r == cj+1) v0.y = 0.f;
            if (r+8 == cj)      v1.x = 0.f;
            else if (r+8 == cj+1) v1.y = 0.f;
            *(float2*)(obase + (size_t)r*C + cj)     = v0;
            *(float2*)(obase + (size_t)(r+8)*C + cj) = v1;

            int m0 = sMask[lc], m1 = sMask[lc+1];
            float2 e0 = make_float2(m0 ? __expf(v0.x) : 0.f, m1 ? __expf(v0.y) : 0.f);
            float2 e1 = make_float2(m0 ? __expf(v1.x) : 0.f, m1 ? __expf(v1.y) : 0.f);
            rp0 += e0.x + e0.y;
            rp1 += e1.x + e1.y;
            __nv_bfloat162 q0, q1;
            q0.x = __float2bfloat16(e0.x); q0.y = __float2bfloat16(e0.y);
            q1.x = __float2bfloat16(e1.x); q1.y = __float2bfloat16(e1.y);
            *(__nv_bfloat162*)(g_E2 + (size_t)b*CC + (size_t)r*C + cj)     = q0;
            *(__nv_bfloat162*)(g_E2 + (size_t)b*CC + (size_t)(r+8)*C + cj) = q1;
        }
        atomicAdd(&sRow[wm*64 + lrow + im*16],     rp0);
        atomicAdd(&sRow[wm*64 + lrow + im*16 + 8], rp1);
    }
    __syncthreads();
    if (tid < 128) atomicAdd(g_sum2 + b*C + it*128 + tid, sRow[tid]);
}

// ============================ h_tmp GEMM (M=128, 2-mma) + m' construction ====
__global__ void __launch_bounds__(256) htmp_mma_kernel(const float* __restrict__ h)
{
    extern __shared__ char smc[];
    int tid = threadIdx.x, wid = tid >> 5, lid = tid & 31;
    int it = blockIdx.x, b = blockIdx.y;
    int wm = wid & 1, wn = wid >> 1;
    uint32_t sb = smem_u32(smc);

    float acc[4][4][4] = {};

    auto issue = [&](int c) {
        size_t offA = ((size_t)b*C + (size_t)it*128)*C + (size_t)c*64;
        size_t offB = (size_t)b*D*C + (size_t)c*64;
        issue_tiles3(sb + (uint32_t)(c % 3)*BUF3_B, tid,
                     g_E2 + offA,
                     g_hThi + offB, g_hTlo + offB, C, C);
    };

    issue(0); CP_COMMIT();
    issue(1); CP_COMMIT();
    for (int c = 0; c < 16; c++) {
        if (c == 15) CP_WAITN(0); else CP_WAITN(1);
        __syncthreads();
        if (c + 2 < 16) { issue(c + 2); CP_COMMIT(); }
        compute_chunk2(sb + (uint32_t)(c % 3)*BUF3_B, acc, wm, wn, lid);
    }

    int lrow = lid >> 2, lcol2 = (lid & 3) << 1;
    int ci0 = it*128 + wm*64 + lrow;
    int d0  = wn*32 + lcol2;
#pragma unroll
    for (int im = 0; im < 4; im++) {
#pragma unroll
        for (int half = 0; half < 2; half++) {
            int cg = ci0 + im*16 + half*8;
            int r  = cg*16 + b;
            float inv = 1.0f / g_sum2[b*C + cg];
#pragma unroll
            for (int jn = 0; jn < 4; jn++) {
                int dj = d0 + jn*8;
                float2 ht = half ? make_float2(acc[im][jn][2], acc[im][jn][3])
                                 : make_float2(acc[im][jn][0], acc[im][jn][1]);
                ht.x *= inv; ht.y *= inv;
                float2 hv = *(const float2*)(h + (size_t)r*128 + dj);
                float2 seg[3];
                seg[0] = hv;
                seg[1] = ht;
                seg[2] = make_float2(hv.x*ht.x, hv.y*ht.y);
#pragma unroll
                for (int s = 0; s < 3; s++) {
                    __nv_bfloat162 hi, lo;
                    split2(seg[s], hi, lo);
                    size_t o = (size_t)r*384 + s*128 + dj;
                    *(__nv_bfloat162*)(g_mhi + o) = hi;
                    *(__nv_bfloat162*)(g_mlo + o) = lo;
                }
            }
        }
    }
}

// ======== fused gate GEMM + combine + sum re-zeroing =========================
__global__ void __launch_bounds__(256) gate_mma_kernel(
    const float* __restrict__ h, float* __restrict__ o)
{
    extern __shared__ char smc[];
    int tid = threadIdx.x, wid = tid >> 5, lid = tid & 31;
    int bm = blockIdx.x;
    int wm = wid & 1, wn = wid >> 1;
    uint32_t sb = smem_u32(smc);

    float accR[4][4][4] = {}, accG[4][4][4] = {};

    auto issue = [&](int c) {
        size_t offA = ((size_t)bm*128)*384 + (size_t)c*64;
        size_t offW = (size_t)c*64;
        issue_gate(sb + (uint32_t)(c & 1)*GSLOT_B, tid,
                   g_mhi + offA, g_mlo + offA,
                   g_Whi + offW, g_Wlo + offW, 384);
    };

    issue(0); CP_COMMIT();
    for (int c = 0; c < 6; c++) {
        CP_WAITN(0);
        __syncthreads();
        if (c + 1 < 6) { issue(c + 1); CP_COMMIT(); }
        compute_gate(sb + (uint32_t)(c & 1)*GSLOT_B, accR, accG, wm, wn, lid);
    }

    int lrow = lid >> 2, lcol2 = (lid & 3) << 1;
    int r0 = bm*128 + wm*64 + lrow;
#pragma unroll
    for (int im = 0; im < 4; im++) {
#pragma unroll
        for (int half = 0; half < 2; half++) {
            int r = r0 + im*16 + half*8;
#pragma unroll
            for (int jn = 0; jn < 4; jn++) {
                int dj = wn*32 + jn*8 + lcol2;
                float zr0 = accR[im][jn][half*2],     zr1 = accR[im][jn][half*2+1];
                float zg0 = accG[im][jn][half*2],     zg1 = accG[im][jn][half*2+1];
                float2 hv = *(const float2*)(h + (size_t)r*128 + dj);
                float x0 = fmaxf(zr0, 0.f), s0 = 1.0f/(1.0f + __expf(-zg0));
                float x1 = fmaxf(zr1, 0.f), s1 = 1.0f/(1.0f + __expf(-zg1));
                float2 ov;
                ov.x = x0*s0 + (1.0f - s0)*hv.x;
                ov.y = x1*s1 + (1.0f - s1)*hv.y;
                *(float2*)(o + (size_t)r*128 + dj) = ov;
            }
        }
    }

    // re-zero sum accumulators for the next invocation (all consumers done)
    int zi = bm*256 + tid;                 // 0 .. 32767 covers 16384 entries
    if (zi < BATCH*C) {
        g_sumF[zi] = 0.f;
        g_sumG[zi] = 0.f;
        g_sum2[zi] = 0.f;
    }
}

// ---------------------------------------------------------------------------
extern "C" void kernel_launch(void* const* d_in, const int* in_sizes, int n_in,
                              void* d_out, int out_size)
{
    const float* h   = (const float*)d_in[0];
    const int*   hm  = (const int*)  d_in[1];
    const float* Bt  = (const float*)d_in[2];
    const float* W1w = (const float*)d_in[3];
    const float* W1b = (const float*)d_in[4];
    const float* W2w = (const float*)d_in[5];
    const float* W2b = (const float*)d_in[6];
    const float* gam = (const float*)d_in[7];
    const float* Wrw = (const float*)d_in[8];
    const float* Wgw = (const float*)d_in[9];

    float* o_out    = (float*)d_out;
    float* bnew_out = (float*)d_out + (size_t)CB*D;

    const int BNEW_SMEM = 3*BUF2_B;        // 110592 -> 2 CTAs/SM
    const int HTMP_SMEM = 3*BUF3_B;        // 165888
    const int GATE_SMEM = 2*GSLOT_B;       // 221184
    cudaFuncSetAttribute(bnew_mma_kernel, cudaFuncAttributeMaxDynamicSharedMemorySize, BNEW_SMEM);
    cudaFuncSetAttribute(htmp_mma_kernel, cudaFuncAttributeMaxDynamicSharedMemorySize, HTMP_SMEM);
    cudaFuncSetAttribute(gate_mma_kernel, cudaFuncAttributeMaxDynamicSharedMemorySize, GATE_SMEM);
    cudaFuncSetAttribute(fc_mma_kernel,  cudaFuncAttributeMaxDynamicSharedMemorySize, GATE_SMEM);

    prep_kernel<<<3456, 256>>>(h, Bt, hm, Wrw, Wgw, W1w, W2w, W1b, W2b);
    fc_mma_kernel<<<CB/128, 256, GATE_SMEM>>>();
    bnew_mma_kernel<<<dim3(C/128, C/128, BATCH), 256, BNEW_SMEM>>>(gam, hm, bnew_out);
    htmp_mma_kernel<<<dim3(C/128, BATCH), 256, HTMP_SMEM>>>(h);
    gate_mma_kernel<<<CB/128, 256, GATE_SMEM>>>(h, o_out);
}